// round 4
// baseline (speedup 1.0000x reference)
#include <cuda_runtime.h>
#include <math.h>

#define NB 16
#define NT 128
#define NI 8
#define ND 128
#define NRB (NT*NB)   // 2048

// scratch (allowed: __device__ globals)
__device__ float g_Xd [NRB*ND];
__device__ float g_T  [NRB*ND];
__device__ float g_Z  [NRB*ND];
__device__ float g_WkT[ND*ND];
__device__ float g_Wqk[ND*ND];
__device__ float g_Wvo[ND*ND];

// mask is a bool array delivered as 32-bit elements (int32 0/1 or float32 0.0/1.0).
__device__ __forceinline__ float mask_f(const unsigned int* __restrict__ m, int idx){
    return (m[idx] != 0u) ? 1.0f : 0.0f;
}

__device__ __forceinline__ float gelu_f(float x){
    // jax gelu (tanh approx) == x * sigmoid(2*g), g = sqrt(2/pi)*(x + 0.044715 x^3)
    float x2 = x*x;
    float g  = x*(0.7978845608028654f + 0.03567740813634427f*x2);
    float e  = __expf(-2.0f*g);
    return x / (1.0f + e);
}

// ---------------------------------------------------------------------------
// x_diag[rb][d]: embed + gelu + mask + LN1 of the diagonal rows
// ---------------------------------------------------------------------------
__global__ void __launch_bounds__(128) k_diag(
    const float* __restrict__ vec, const unsigned int* __restrict__ mask,
    const float* __restrict__ We,  const float* __restrict__ be,
    const float* __restrict__ g1,  const float* __restrict__ b1)
{
    int rb = blockIdx.x; int r = rb >> 4; int b = rb & 15;
    int d  = threadIdx.x;
    __shared__ float v8[8];
    __shared__ float red[8];
    const float* vp = vec + ((b*NT + r)*NT + r)*NI;
    if (d < 8) v8[d] = vp[d];
    float mf = mask_f(mask, (b*NT + r)*NT + r);
    __syncthreads();
    float y = be[d];
    #pragma unroll
    for (int i = 0; i < 8; i++) y += v8[i]*We[i*ND + d];
    y = gelu_f(y) * mf;
    float s1 = y, s2 = y*y;
    #pragma unroll
    for (int o = 16; o; o >>= 1){
        s1 += __shfl_xor_sync(0xffffffffu, s1, o);
        s2 += __shfl_xor_sync(0xffffffffu, s2, o);
    }
    int w = d >> 5, lane = d & 31;
    if (lane == 0){ red[w] = s1; red[4+w] = s2; }
    __syncthreads();
    s1 = red[0]+red[1]+red[2]+red[3];
    s2 = red[4]+red[5]+red[6]+red[7];
    float mu  = s1 * (1.0f/128.0f);
    float var = s2 * (1.0f/128.0f) - mu*mu;
    float o   = (y - mu)*rsqrtf(var + 1e-5f)*g1[d] + b1[d];
    g_Xd[rb*ND + d] = o;
}

// ---------------------------------------------------------------------------
// transpose Wk -> g_WkT
// ---------------------------------------------------------------------------
__global__ void k_tr(const float* __restrict__ Wk)
{
    __shared__ float t[32][33];
    int tx = threadIdx.x, ty = threadIdx.y;
    int x  = blockIdx.x*32 + tx;
    int y0 = blockIdx.y*32;
    #pragma unroll
    for (int j = 0; j < 32; j += 8)
        t[ty + j][tx] = Wk[(y0 + ty + j)*ND + x];
    __syncthreads();
    int xo  = blockIdx.y*32 + tx;
    int yo0 = blockIdx.x*32;
    #pragma unroll
    for (int j = 0; j < 32; j += 8)
        g_WkT[(yo0 + ty + j)*ND + xo] = t[tx][ty + j];
}

// ---------------------------------------------------------------------------
// Wqk = Wq @ Wk^T, Wvo = Wv @ Wo
// ---------------------------------------------------------------------------
__global__ void __launch_bounds__(128) k_prep(
    const float* __restrict__ Wq, const float* __restrict__ Wv,
    const float* __restrict__ Wo)
{
    __shared__ float sq[128], sv[128];
    int m = blockIdx.x, n = threadIdx.x;
    sq[n] = Wq[m*ND + n];
    sv[n] = Wv[m*ND + n];
    __syncthreads();
    float aq0 = 0.f, aq1 = 0.f, av0 = 0.f, av1 = 0.f;
    #pragma unroll 4
    for (int e = 0; e < 128; e += 2){
        aq0 += sq[e  ]*g_WkT[(e  )*ND + n];
        aq1 += sq[e+1]*g_WkT[(e+1)*ND + n];
        av0 += sv[e  ]*Wo  [(e  )*ND + n];
        av1 += sv[e+1]*Wo  [(e+1)*ND + n];
    }
    g_Wqk[m*ND + n] = aq0 + aq1;
    g_Wvo[m*ND + n] = av0 + av1;
}

// ---------------------------------------------------------------------------
// T = Xd @ Wqk   (8-row tiles, 256 CTAs x 128 thr)
// ---------------------------------------------------------------------------
__global__ void __launch_bounds__(128) k_qt()
{
    __shared__ float sA[8*132];
    int tid = threadIdx.x;
    int rb0 = blockIdx.x*8;
    for (int idx = tid; idx < 8*128; idx += 128){
        int row = idx >> 7, col = idx & 127;
        sA[row*132 + col] = g_Xd[(rb0+row)*ND + col];
    }
    __syncthreads();
    int ty = tid >> 4, tx = tid & 15;
    float acc[8];
    #pragma unroll
    for (int j = 0; j < 8; j++) acc[j] = 0.0f;
    const float* Bb = g_Wqk + 8*tx;
    #pragma unroll 4
    for (int k = 0; k < 128; k++){
        float a = sA[ty*132 + k];
        float4 b0 = *(const float4*)(Bb + k*ND);
        float4 b1 = *(const float4*)(Bb + k*ND + 4);
        acc[0] += a*b0.x; acc[1] += a*b0.y; acc[2] += a*b0.z; acc[3] += a*b0.w;
        acc[4] += a*b1.x; acc[5] += a*b1.y; acc[6] += a*b1.z; acc[7] += a*b1.w;
    }
    #pragma unroll
    for (int j = 0; j < 8; j++)
        g_T[(rb0+ty)*ND + 8*tx + j] = acc[j];
}

// ---------------------------------------------------------------------------
// Fused attention: per (r,b) recompute x rows in 64-row chunks, online softmax,
// z[rb][d] = sum_c softmax(x_row . t)[c] * x_row[c][d]
// 256 threads: 4 threads per c-row (cl=tid>>2), each owns contiguous d-block of 32.
// ---------------------------------------------------------------------------
__global__ void __launch_bounds__(256) k_attn(
    const float* __restrict__ vec, const unsigned int* __restrict__ mask,
    const float* __restrict__ We,  const float* __restrict__ be,
    const float* __restrict__ g1,  const float* __restrict__ b1)
{
    __shared__ float sWe[8*128];
    __shared__ float sbe[128], sg1[128], sb1[128];
    __shared__ float ts[128];
    __shared__ float sxs[64*132];
    __shared__ float sv8[64*8];
    __shared__ float smk[64];
    __shared__ float slg[64];
    __shared__ float sw[64];
    __shared__ float sml[2];
    __shared__ float sred[128];

    int tid = threadIdx.x;
    int rb = blockIdx.x; int r = rb >> 4; int b = rb & 15;

    for (int idx = tid; idx < 1024; idx += 256) sWe[idx] = We[idx];
    if (tid < 128){
        sbe[tid] = be[tid]; sg1[tid] = g1[tid]; sb1[tid] = b1[tid];
        ts[tid]  = g_T[rb*ND + tid] * 0.08838834764831845f;   // 1/sqrt(128)
    }
    __syncthreads();

    int cl = tid >> 2, q = tid & 3;
    int d0 = 32*q;
    int dz = tid & 127, h = tid >> 7;
    const float* vbase = vec + ((b*NT + r)*NT)*NI;
    const unsigned int* mbase = mask + (b*NT + r)*NT;

    float m_run = -INFINITY, l_run = 0.0f;   // meaningful in warp0 only
    float zacc = 0.0f;

    #pragma unroll
    for (int c0 = 0; c0 < NT; c0 += 64){
        for (int idx = tid; idx < 512; idx += 256) sv8[idx] = vbase[c0*NI + idx];
        if (tid < 64) smk[tid] = mask_f(mbase, c0 + tid);
        __syncthreads();

        float4 vA = *(const float4*)(sv8 + cl*8);
        float4 vB = *(const float4*)(sv8 + cl*8 + 4);
        float v8r[8] = {vA.x,vA.y,vA.z,vA.w,vB.x,vB.y,vB.z,vB.w};
        float mf = smk[cl];
        float y[32];
        float s1 = 0.0f, s2 = 0.0f;
        #pragma unroll
        for (int jj = 0; jj < 8; jj++){
            int d = d0 + 4*jj;
            float4 a4 = *(const float4*)(sbe + d);
            #pragma unroll
            for (int i = 0; i < 8; i++){
                float4 w4 = *(const float4*)(sWe + i*128 + d);
                a4.x += v8r[i]*w4.x; a4.y += v8r[i]*w4.y;
                a4.z += v8r[i]*w4.z; a4.w += v8r[i]*w4.w;
            }
            a4.x = gelu_f(a4.x)*mf; a4.y = gelu_f(a4.y)*mf;
            a4.z = gelu_f(a4.z)*mf; a4.w = gelu_f(a4.w)*mf;
            y[4*jj+0] = a4.x; y[4*jj+1] = a4.y; y[4*jj+2] = a4.z; y[4*jj+3] = a4.w;
            s1 += a4.x + a4.y + a4.z + a4.w;
            s2 += a4.x*a4.x + a4.y*a4.y + a4.z*a4.z + a4.w*a4.w;
        }
        s1 += __shfl_xor_sync(0xffffffffu, s1, 1); s2 += __shfl_xor_sync(0xffffffffu, s2, 1);
        s1 += __shfl_xor_sync(0xffffffffu, s1, 2); s2 += __shfl_xor_sync(0xffffffffu, s2, 2);
        float mu   = s1*(1.0f/128.0f);
        float var  = s2*(1.0f/128.0f) - mu*mu;
        float rstd = rsqrtf(var + 1e-5f);
        float dotp = 0.0f;
        #pragma unroll
        for (int jj = 0; jj < 8; jj++){
            int d = d0 + 4*jj;
            float4 t4 = *(const float4*)(ts  + d);
            float4 g4 = *(const float4*)(sg1 + d);
            float4 b4 = *(const float4*)(sb1 + d);
            float4 x4;
            x4.x = (y[4*jj+0]-mu)*rstd*g4.x + b4.x;
            x4.y = (y[4*jj+1]-mu)*rstd*g4.y + b4.y;
            x4.z = (y[4*jj+2]-mu)*rstd*g4.z + b4.z;
            x4.w = (y[4*jj+3]-mu)*rstd*g4.w + b4.w;
            *(float4*)(sxs + cl*132 + d) = x4;
            dotp += x4.x*t4.x + x4.y*t4.y + x4.z*t4.z + x4.w*t4.w;
        }
        dotp += __shfl_xor_sync(0xffffffffu, dotp, 1);
        dotp += __shfl_xor_sync(0xffffffffu, dotp, 2);
        bool am = (mf != 0.0f) || (c0 + cl == r);
        float lg = dotp + (am ? 0.0f : -1e9f);
        if (q == 0) slg[cl] = lg;
        __syncthreads();

        if (tid < 32){
            float lg0 = slg[tid], lg1 = slg[tid+32];
            float cm = fmaxf(lg0, lg1);
            #pragma unroll
            for (int o = 16; o; o >>= 1) cm = fmaxf(cm, __shfl_xor_sync(0xffffffffu, cm, o));
            float m_new = fmaxf(m_run, cm);
            float corr  = __expf(m_run - m_new);
            float w0    = __expf(lg0 - m_new);
            float w1    = __expf(lg1 - m_new);
            float s = w0 + w1;
            #pragma unroll
            for (int o = 16; o; o >>= 1) s += __shfl_xor_sync(0xffffffffu, s, o);
            sw[tid] = w0; sw[tid+32] = w1;
            l_run = l_run*corr + s;
            m_run = m_new;
            if (tid == 0) sml[0] = corr;
        }
        __syncthreads();
        float corr = sml[0];
        zacc *= corr;
        int cb = h*32;
        #pragma unroll
        for (int c = 0; c < 32; c++) zacc += sw[cb+c]*sxs[(cb+c)*132 + dz];
        __syncthreads();
    }
    if (tid == 0) sml[1] = l_run;
    if (h == 1) sred[dz] = zacc;
    __syncthreads();
    if (h == 0) g_Z[rb*ND + dz] = (zacc + sred[dz]) / sml[1];
}

// ---------------------------------------------------------------------------
// [E|G] = Z @ [Wv|Wvo] ; t = gelu(G+bo)+E ; out = LN2(t)*seq
// 8-row tiles, 256 CTAs x 256 thr
// ---------------------------------------------------------------------------
__global__ void __launch_bounds__(256) k_out(
    const float* __restrict__ Wv, const float* __restrict__ bo,
    const float* __restrict__ g2, const float* __restrict__ b2,
    const unsigned int* __restrict__ mask, float* __restrict__ out)
{
    __shared__ float sZ[8*132];
    __shared__ float sE[8*132];
    __shared__ float sG[8*132];
    int tid = threadIdx.x;
    int rb0 = blockIdx.x*8;
    for (int idx = tid; idx < 8*128; idx += 256){
        int row = idx >> 7, col = idx & 127;
        sZ[row*132 + col] = g_Z[(rb0+row)*ND + col];
    }
    __syncthreads();
    int ty = tid >> 5, tx = tid & 31;
    const float* Bb = (tx < 16) ? (Wv + 8*tx) : (g_Wvo + 8*(tx-16));
    float acc[8];
    #pragma unroll
    for (int j = 0; j < 8; j++) acc[j] = 0.0f;
    #pragma unroll 4
    for (int k = 0; k < 128; k++){
        float a = sZ[ty*132 + k];
        float4 b0 = *(const float4*)(Bb + k*ND);
        float4 b1 = *(const float4*)(Bb + k*ND + 4);
        acc[0] += a*b0.x; acc[1] += a*b0.y; acc[2] += a*b0.z; acc[3] += a*b0.w;
        acc[4] += a*b1.x; acc[5] += a*b1.y; acc[6] += a*b1.z; acc[7] += a*b1.w;
    }
    float* dst = (tx < 16) ? (sE + ty*132 + 8*tx) : (sG + ty*132 + 8*(tx-16));
    #pragma unroll
    for (int j = 0; j < 8; j++) dst[j] = acc[j];
    __syncthreads();

    // epilogue: warp w handles row w; lane owns d = lane + 32*j
    int w = ty, lane = tx;
    float tv[4];
    float s1 = 0.0f, s2 = 0.0f;
    #pragma unroll
    for (int j = 0; j < 4; j++){
        int d = lane + 32*j;
        float t = gelu_f(sG[w*132 + d] + bo[d]) + sE[w*132 + d];
        tv[j] = t; s1 += t; s2 += t*t;
    }
    #pragma unroll
    for (int o = 16; o; o >>= 1){
        s1 += __shfl_xor_sync(0xffffffffu, s1, o);
        s2 += __shfl_xor_sync(0xffffffffu, s2, o);
    }
    float mu   = s1*(1.0f/128.0f);
    float var  = s2*(1.0f/128.0f) - mu*mu;
    float rstd = rsqrtf(var + 1e-5f);
    int rbg = rb0 + w; int r = rbg >> 4, bb = rbg & 15;
    float sf = mask_f(mask, (bb*NT + r)*NT + r);
    #pragma unroll
    for (int j = 0; j < 4; j++){
        int d = lane + 32*j;
        out[rbg*ND + d] = ((tv[j] - mu)*rstd*g2[d] + b2[d])*sf;
    }
}

// ---------------------------------------------------------------------------
// bool outputs as float: padding_mask (B,T), sequence_mask (T,B,1), global (T)
// ---------------------------------------------------------------------------
__global__ void k_masks(const unsigned int* __restrict__ mask, float* __restrict__ out)
{
    int idx = blockIdx.x*blockDim.x + threadIdx.x;
    if (idx < 2048){
        int b = idx >> 7, t = idx & 127;
        out[262144 + idx] = (mask[(b*NT + t)*NT + t] != 0u) ? 0.0f : 1.0f;   // ~seq^T
    } else if (idx < 4096){
        int k = idx - 2048; int t = k >> 4, b = k & 15;
        out[264192 + k] = (mask[(b*NT + t)*NT + t] != 0u) ? 1.0f : 0.0f;     // seq
    } else if (idx < 4224){
        out[266240 + (idx - 4096)] = 1.0f;                                    // ones
    }
}

extern "C" void kernel_launch(void* const* d_in, const int* in_sizes, int n_in,
                              void* d_out, int out_size)
{
    const float*        vec  = (const float*)d_in[0];
    const unsigned int* mask = (const unsigned int*)d_in[1];
    const float* We = (const float*)d_in[2];
    const float* be = (const float*)d_in[3];
    const float* g1 = (const float*)d_in[4];
    const float* b1 = (const float*)d_in[5];
    const float* Wq = (const float*)d_in[6];
    const float* Wk = (const float*)d_in[7];
    const float* Wv = (const float*)d_in[8];
    const float* Wo = (const float*)d_in[9];
    const float* bo = (const float*)d_in[10];
    const float* g2 = (const float*)d_in[11];
    const float* b2 = (const float*)d_in[12];
    float* out = (float*)d_out;

    k_tr  <<<dim3(4,4), dim3(32,8)>>>(Wk);
    k_diag<<<NRB, 128>>>(vec, mask, We, be, g1, b1);
    k_prep<<<128, 128>>>(Wq, Wv, Wo);
    k_qt  <<<NRB/8, 128>>>();
    k_attn<<<NRB, 256>>>(vec, mask, We, be, g1, b1);
    k_out <<<NRB/8, 256>>>(Wv, bo, g2, b2, mask, out);
    if (out_size >= 266368)
        k_masks<<<17, 256>>>(mask, out);
    (void)in_sizes; (void)n_in;
}

// round 5
// speedup vs baseline: 2.4394x; 2.4394x over previous
#include <cuda_runtime.h>
#include <math.h>

#define NB 16
#define NT 128
#define NI 8
#define ND 128
#define NRB (NT*NB)   // 2048

// scratch (allowed: __device__ globals)
__device__ float g_Xd [NRB*ND];
__device__ float g_T  [NRB*ND];
__device__ float g_Z  [NRB*ND];
__device__ float g_WkT[ND*ND];
__device__ float g_Wqk[ND*ND];
__device__ float g_Wvo[ND*ND];

// mask is a bool array delivered as 32-bit elements (int32 0/1 or float32 0.0/1.0).
__device__ __forceinline__ float mask_f(const unsigned int* __restrict__ m, int idx){
    return (m[idx] != 0u) ? 1.0f : 0.0f;
}

__device__ __forceinline__ float gelu_f(float x){
    // jax gelu (tanh approx) == x * sigmoid(2*g), g = sqrt(2/pi)*(x + 0.044715 x^3)
    float x2 = x*x;
    float g  = x*(0.7978845608028654f + 0.03567740813634427f*x2);
    float e  = __expf(-2.0f*g);
    return x / (1.0f + e);
}

// ---------------------------------------------------------------------------
// x_diag[rb][d]: embed + gelu + mask + LN1 of the diagonal rows
// ---------------------------------------------------------------------------
__global__ void __launch_bounds__(128) k_diag(
    const float* __restrict__ vec, const unsigned int* __restrict__ mask,
    const float* __restrict__ We,  const float* __restrict__ be,
    const float* __restrict__ g1,  const float* __restrict__ b1)
{
    int rb = blockIdx.x; int r = rb >> 4; int b = rb & 15;
    int d  = threadIdx.x;
    __shared__ float v8[8];
    __shared__ float red[8];
    const float* vp = vec + ((b*NT + r)*NT + r)*NI;
    if (d < 8) v8[d] = vp[d];
    float mf = mask_f(mask, (b*NT + r)*NT + r);
    __syncthreads();
    float y = be[d];
    #pragma unroll
    for (int i = 0; i < 8; i++) y += v8[i]*We[i*ND + d];
    y = gelu_f(y) * mf;
    float s1 = y, s2 = y*y;
    #pragma unroll
    for (int o = 16; o; o >>= 1){
        s1 += __shfl_xor_sync(0xffffffffu, s1, o);
        s2 += __shfl_xor_sync(0xffffffffu, s2, o);
    }
    int w = d >> 5, lane = d & 31;
    if (lane == 0){ red[w] = s1; red[4+w] = s2; }
    __syncthreads();
    s1 = red[0]+red[1]+red[2]+red[3];
    s2 = red[4]+red[5]+red[6]+red[7];
    float mu  = s1 * (1.0f/128.0f);
    float var = s2 * (1.0f/128.0f) - mu*mu;
    float o   = (y - mu)*rsqrtf(var + 1e-5f)*g1[d] + b1[d];
    g_Xd[rb*ND + d] = o;
}

// ---------------------------------------------------------------------------
// transpose Wk -> g_WkT
// ---------------------------------------------------------------------------
__global__ void k_tr(const float* __restrict__ Wk)
{
    __shared__ float t[32][33];
    int tx = threadIdx.x, ty = threadIdx.y;
    int x  = blockIdx.x*32 + tx;
    int y0 = blockIdx.y*32;
    #pragma unroll
    for (int j = 0; j < 32; j += 8)
        t[ty + j][tx] = Wk[(y0 + ty + j)*ND + x];
    __syncthreads();
    int xo  = blockIdx.y*32 + tx;
    int yo0 = blockIdx.x*32;
    #pragma unroll
    for (int j = 0; j < 32; j += 8)
        g_WkT[(yo0 + ty + j)*ND + xo] = t[tx][ty + j];
}

// ---------------------------------------------------------------------------
// Wqk = Wq @ Wk^T, Wvo = Wv @ Wo
// ---------------------------------------------------------------------------
__global__ void __launch_bounds__(128) k_prep(
    const float* __restrict__ Wq, const float* __restrict__ Wv,
    const float* __restrict__ Wo)
{
    __shared__ float sq[128], sv[128];
    int m = blockIdx.x, n = threadIdx.x;
    sq[n] = Wq[m*ND + n];
    sv[n] = Wv[m*ND + n];
    __syncthreads();
    float aq0 = 0.f, aq1 = 0.f, av0 = 0.f, av1 = 0.f;
    #pragma unroll 8
    for (int e = 0; e < 128; e += 2){
        aq0 += sq[e  ]*g_WkT[(e  )*ND + n];
        aq1 += sq[e+1]*g_WkT[(e+1)*ND + n];
        av0 += sv[e  ]*Wo  [(e  )*ND + n];
        av1 += sv[e+1]*Wo  [(e+1)*ND + n];
    }
    g_Wqk[m*ND + n] = aq0 + aq1;
    g_Wvo[m*ND + n] = av0 + av1;
}

// ---------------------------------------------------------------------------
// T = Xd @ Wqk  — tiled GEMM, 16-row CTAs (grid 128), both operands in smem
// ---------------------------------------------------------------------------
__global__ void __launch_bounds__(256) k_qt()
{
    __shared__ float sA[16*33];
    __shared__ float sB[32*132];
    int tid = threadIdx.x;
    int rb0 = blockIdx.x*16;
    int tx = tid & 31, ty = tid >> 5;           // ty: 8 row-pairs, tx: 32 col-quads
    int r0 = ty*2, r1 = r0 + 1, c4 = tx*4;
    float acc[8];
    #pragma unroll
    for (int j = 0; j < 8; j++) acc[j] = 0.0f;

    for (int k0 = 0; k0 < 128; k0 += 32){
        #pragma unroll
        for (int i = 0; i < 2; i++){
            int idx = tid + i*256; int row = idx >> 5, kk = idx & 31;
            sA[row*33 + kk] = g_Xd[(rb0+row)*ND + k0 + kk];
        }
        #pragma unroll
        for (int i = 0; i < 4; i++){
            int fi = tid + i*256; int kk = fi >> 5, cf = fi & 31;
            *(float4*)&sB[kk*132 + cf*4] = *(const float4*)(g_Wqk + (k0+kk)*ND + cf*4);
        }
        __syncthreads();
        #pragma unroll
        for (int kk = 0; kk < 32; kk++){
            float a0 = sA[r0*33 + kk], a1 = sA[r1*33 + kk];
            float4 b = *(float4*)&sB[kk*132 + c4];
            acc[0] += a0*b.x; acc[1] += a0*b.y; acc[2] += a0*b.z; acc[3] += a0*b.w;
            acc[4] += a1*b.x; acc[5] += a1*b.y; acc[6] += a1*b.z; acc[7] += a1*b.w;
        }
        __syncthreads();
    }
    *(float4*)&g_T[(rb0+r0)*ND + c4] = make_float4(acc[0],acc[1],acc[2],acc[3]);
    *(float4*)&g_T[(rb0+r1)*ND + c4] = make_float4(acc[4],acc[5],acc[6],acc[7]);
}

// ---------------------------------------------------------------------------
// Fused attention, flat softmax. One CTA per (r,b), 256 threads, dyn smem.
// 2 threads per c-row; x rows staged in smem; z = softmax-weighted sum.
// ---------------------------------------------------------------------------
#define ATTN_SMEM 75280
__global__ void __launch_bounds__(256) k_attn(
    const float* __restrict__ vec, const unsigned int* __restrict__ mask,
    const float* __restrict__ We,  const float* __restrict__ be,
    const float* __restrict__ g1,  const float* __restrict__ b1)
{
    extern __shared__ float sm[];
    float* sWe  = sm;               // 1024
    float* sbe  = sWe  + 1024;      // 128
    float* sg1  = sbe  + 128;       // 128
    float* sb1  = sg1  + 128;       // 128
    float* ts   = sb1  + 128;       // 128
    float* slg  = ts   + 128;       // 128
    float* sw   = slg  + 128;       // 128
    float* sred = sw   + 128;       // 128
    float* sml  = sred + 128;       // 4
    float* sxs  = sml  + 4;         // 128*132

    int tid = threadIdx.x;
    int rb = blockIdx.x; int r = rb >> 4; int b = rb & 15;

    #pragma unroll
    for (int i = 0; i < 4; i++) sWe[tid + i*256] = We[tid + i*256];
    if (tid < 128){
        sbe[tid] = be[tid]; sg1[tid] = g1[tid]; sb1[tid] = b1[tid];
        ts[tid]  = g_T[rb*ND + tid] * 0.08838834764831845f;   // 1/sqrt(128)
    }
    __syncthreads();

    // phase 1: embed+gelu+LN1 for c-row = tid>>1, d-half = tid&1
    int row = tid >> 1, half = tid & 1, d0 = 64*half;
    const float* vp = vec + (((b*NT + r)*NT) + row)*NI;
    float4 vA = *(const float4*)vp;
    float4 vB = *(const float4*)(vp + 4);
    float v8r[8] = {vA.x,vA.y,vA.z,vA.w,vB.x,vB.y,vB.z,vB.w};
    float mf = mask_f(mask, (b*NT + r)*NT + row);

    float y[64];
    float s1 = 0.0f, s2 = 0.0f;
    #pragma unroll
    for (int j = 0; j < 16; j++){
        int d = d0 + 4*j;
        float4 a4 = *(const float4*)(sbe + d);
        #pragma unroll
        for (int i = 0; i < 8; i++){
            float4 w4 = *(const float4*)(sWe + i*128 + d);
            a4.x += v8r[i]*w4.x; a4.y += v8r[i]*w4.y;
            a4.z += v8r[i]*w4.z; a4.w += v8r[i]*w4.w;
        }
        a4.x = gelu_f(a4.x)*mf; a4.y = gelu_f(a4.y)*mf;
        a4.z = gelu_f(a4.z)*mf; a4.w = gelu_f(a4.w)*mf;
        y[4*j+0]=a4.x; y[4*j+1]=a4.y; y[4*j+2]=a4.z; y[4*j+3]=a4.w;
        s1 += a4.x + a4.y + a4.z + a4.w;
        s2 += a4.x*a4.x + a4.y*a4.y + a4.z*a4.z + a4.w*a4.w;
    }
    s1 += __shfl_xor_sync(0xffffffffu, s1, 1);
    s2 += __shfl_xor_sync(0xffffffffu, s2, 1);
    float mu   = s1*(1.0f/128.0f);
    float var  = s2*(1.0f/128.0f) - mu*mu;
    float rstd = rsqrtf(var + 1e-5f);
    float dotp = 0.0f;
    #pragma unroll
    for (int j = 0; j < 16; j++){
        int d = d0 + 4*j;
        float4 g4 = *(const float4*)(sg1 + d);
        float4 b4 = *(const float4*)(sb1 + d);
        float4 t4 = *(const float4*)(ts  + d);
        float4 x4;
        x4.x = (y[4*j+0]-mu)*rstd*g4.x + b4.x;
        x4.y = (y[4*j+1]-mu)*rstd*g4.y + b4.y;
        x4.z = (y[4*j+2]-mu)*rstd*g4.z + b4.z;
        x4.w = (y[4*j+3]-mu)*rstd*g4.w + b4.w;
        *(float4*)(sxs + row*132 + d) = x4;
        dotp += x4.x*t4.x + x4.y*t4.y + x4.z*t4.z + x4.w*t4.w;
    }
    dotp += __shfl_xor_sync(0xffffffffu, dotp, 1);
    bool am = (mf != 0.0f) || (row == r);
    if (half == 0) slg[row] = dotp + (am ? 0.0f : -1e9f);
    __syncthreads();

    // phase 2: flat softmax over 128 logits (warp 0)
    if (tid < 32){
        float lgv[4];
        #pragma unroll
        for (int k = 0; k < 4; k++) lgv[k] = slg[tid + 32*k];
        float m = fmaxf(fmaxf(lgv[0],lgv[1]), fmaxf(lgv[2],lgv[3]));
        #pragma unroll
        for (int o = 16; o; o >>= 1) m = fmaxf(m, __shfl_xor_sync(0xffffffffu, m, o));
        float e[4], s = 0.0f;
        #pragma unroll
        for (int k = 0; k < 4; k++){ e[k] = __expf(lgv[k]-m); s += e[k]; }
        #pragma unroll
        for (int o = 16; o; o >>= 1) s += __shfl_xor_sync(0xffffffffu, s, o);
        #pragma unroll
        for (int k = 0; k < 4; k++) sw[tid + 32*k] = e[k];
        if (tid == 0) sml[0] = s;
    }
    __syncthreads();

    // phase 3: z[dz] = sum_c w[c] * x[c][dz]
    int dz = tid & 127, h = tid >> 7;
    float z = 0.0f;
    const float* xp = sxs + (h*64)*132 + dz;
    const float* wp = sw + h*64;
    #pragma unroll 8
    for (int c = 0; c < 64; c++) z += wp[c]*xp[c*132];
    if (h == 1) sred[dz] = z;
    __syncthreads();
    if (h == 0) g_Z[rb*ND + dz] = (z + sred[dz]) / sml[0];
}

// ---------------------------------------------------------------------------
// [E|G] = Z @ [Wv|Wvo]; t = gelu(G+bo)+E; out = LN2(t)*seq
// 16-row CTAs (grid 128), tiled GEMM N=256, B in smem, C reuses B smem
// ---------------------------------------------------------------------------
__global__ void __launch_bounds__(256) k_out(
    const float* __restrict__ Wv, const float* __restrict__ bo,
    const float* __restrict__ g2, const float* __restrict__ b2,
    const unsigned int* __restrict__ mask, float* __restrict__ out)
{
    __shared__ float sA[16*33];
    __shared__ float sB[32*260];    // also reused as sC[16*260] post-loop
    int tid = threadIdx.x;
    int rb0 = blockIdx.x*16;
    int tx = tid & 31, ty = tid >> 5;
    int r0 = ty*2, r1 = r0 + 1, c8 = tx*8;
    float acc[16];
    #pragma unroll
    for (int j = 0; j < 16; j++) acc[j] = 0.0f;

    for (int k0 = 0; k0 < 128; k0 += 32){
        #pragma unroll
        for (int i = 0; i < 2; i++){
            int idx = tid + i*256; int row = idx >> 5, kk = idx & 31;
            sA[row*33 + kk] = g_Z[(rb0+row)*ND + k0 + kk];
        }
        #pragma unroll
        for (int i = 0; i < 8; i++){
            int fi = tid + i*256; int kk = fi >> 6, cf = fi & 63;
            const float* src = (cf < 32) ? (Wv + (k0+kk)*ND + cf*4)
                                         : (g_Wvo + (k0+kk)*ND + (cf-32)*4);
            *(float4*)&sB[kk*260 + cf*4] = *(const float4*)src;
        }
        __syncthreads();
        #pragma unroll
        for (int kk = 0; kk < 32; kk++){
            float a0 = sA[r0*33 + kk], a1 = sA[r1*33 + kk];
            float4 bx = *(float4*)&sB[kk*260 + c8];
            float4 by = *(float4*)&sB[kk*260 + c8 + 4];
            acc[0] += a0*bx.x; acc[1] += a0*bx.y; acc[2] += a0*bx.z; acc[3] += a0*bx.w;
            acc[4] += a0*by.x; acc[5] += a0*by.y; acc[6] += a0*by.z; acc[7] += a0*by.w;
            acc[8] += a1*bx.x; acc[9] += a1*bx.y; acc[10]+= a1*bx.z; acc[11]+= a1*bx.w;
            acc[12]+= a1*by.x; acc[13]+= a1*by.y; acc[14]+= a1*by.z; acc[15]+= a1*by.w;
        }
        __syncthreads();
    }
    // stage C into reused sB
    *(float4*)&sB[r0*260 + c8    ] = make_float4(acc[0],acc[1],acc[2],acc[3]);
    *(float4*)&sB[r0*260 + c8 + 4] = make_float4(acc[4],acc[5],acc[6],acc[7]);
    *(float4*)&sB[r1*260 + c8    ] = make_float4(acc[8],acc[9],acc[10],acc[11]);
    *(float4*)&sB[r1*260 + c8 + 4] = make_float4(acc[12],acc[13],acc[14],acc[15]);
    __syncthreads();

    // epilogue: warp ty handles rows r0,r1; lane owns d-quad tx*4
    int d4 = tx*4;
    float4 bo4 = *(const float4*)(bo + d4);
    float4 g24 = *(const float4*)(g2 + d4);
    float4 b24 = *(const float4*)(b2 + d4);
    #pragma unroll
    for (int rr = 0; rr < 2; rr++){
        int row = ty*2 + rr;
        float4 E = *(float4*)&sB[row*260 + d4];
        float4 G = *(float4*)&sB[row*260 + 128 + d4];
        float4 t;
        t.x = gelu_f(G.x + bo4.x) + E.x;
        t.y = gelu_f(G.y + bo4.y) + E.y;
        t.z = gelu_f(G.z + bo4.z) + E.z;
        t.w = gelu_f(G.w + bo4.w) + E.w;
        float s1 = t.x + t.y + t.z + t.w;
        float s2 = t.x*t.x + t.y*t.y + t.z*t.z + t.w*t.w;
        #pragma unroll
        for (int o = 16; o; o >>= 1){
            s1 += __shfl_xor_sync(0xffffffffu, s1, o);
            s2 += __shfl_xor_sync(0xffffffffu, s2, o);
        }
        float mu   = s1*(1.0f/128.0f);
        float var  = s2*(1.0f/128.0f) - mu*mu;
        float rstd = rsqrtf(var + 1e-5f);
        int rbg = rb0 + row; int r = rbg >> 4, bb = rbg & 15;
        float sf = mask_f(mask, (bb*NT + r)*NT + r);
        float4 o4;
        o4.x = ((t.x - mu)*rstd*g24.x + b24.x)*sf;
        o4.y = ((t.y - mu)*rstd*g24.y + b24.y)*sf;
        o4.z = ((t.z - mu)*rstd*g24.z + b24.z)*sf;
        o4.w = ((t.w - mu)*rstd*g24.w + b24.w)*sf;
        *(float4*)(out + rbg*ND + d4) = o4;
    }
}

// ---------------------------------------------------------------------------
// bool outputs as float: padding_mask (B,T), sequence_mask (T,B,1), global (T)
// ---------------------------------------------------------------------------
__global__ void k_masks(const unsigned int* __restrict__ mask, float* __restrict__ out)
{
    int idx = blockIdx.x*blockDim.x + threadIdx.x;
    if (idx < 2048){
        int b = idx >> 7, t = idx & 127;
        out[262144 + idx] = (mask[(b*NT + t)*NT + t] != 0u) ? 0.0f : 1.0f;   // ~seq^T
    } else if (idx < 4096){
        int k = idx - 2048; int t = k >> 4, b = k & 15;
        out[264192 + k] = (mask[(b*NT + t)*NT + t] != 0u) ? 1.0f : 0.0f;     // seq
    } else if (idx < 4224){
        out[266240 + (idx - 4096)] = 1.0f;                                    // ones
    }
}

extern "C" void kernel_launch(void* const* d_in, const int* in_sizes, int n_in,
                              void* d_out, int out_size)
{
    const float*        vec  = (const float*)d_in[0];
    const unsigned int* mask = (const unsigned int*)d_in[1];
    const float* We = (const float*)d_in[2];
    const float* be = (const float*)d_in[3];
    const float* g1 = (const float*)d_in[4];
    const float* b1 = (const float*)d_in[5];
    const float* Wq = (const float*)d_in[6];
    const float* Wk = (const float*)d_in[7];
    const float* Wv = (const float*)d_in[8];
    const float* Wo = (const float*)d_in[9];
    const float* bo = (const float*)d_in[10];
    const float* g2 = (const float*)d_in[11];
    const float* b2 = (const float*)d_in[12];
    float* out = (float*)d_out;

    cudaFuncSetAttribute(k_attn, cudaFuncAttributeMaxDynamicSharedMemorySize, ATTN_SMEM);

    k_tr  <<<dim3(4,4), dim3(32,8)>>>(Wk);
    k_diag<<<NRB, 128>>>(vec, mask, We, be, g1, b1);
    k_prep<<<128, 128>>>(Wq, Wv, Wo);
    k_qt  <<<NRB/16, 256>>>();
    k_attn<<<NRB, 256, ATTN_SMEM>>>(vec, mask, We, be, g1, b1);
    k_out <<<NRB/16, 256>>>(Wv, bo, g2, b2, mask, out);
    if (out_size >= 266368)
        k_masks<<<17, 256>>>(mask, out);
    (void)in_sizes; (void)n_in;
}